// round 10
// baseline (speedup 1.0000x reference)
#include <cuda_runtime.h>

// Problem constants
#define BSZ     256
#define IDIM    182
#define TSTEPS  2000
#define H0LEN   1024         // half 0: t in [0,1024)    -- 128B-aligned rows
#define H1LEN   976          // half 1: t in [1024,2000) -- base offset 4096B, aligned
#define OCH     2
#define CHUNK   2            // steps per thread in scan phase
#define NTHR    512
#define NW      16           // warps per CTA
#define GRID    (BSZ * 2)    // CTA 2b+h: batch b, t-half h

// boundary handoff: half-0 final state (syn0,mem0,syn1,mem1) + flag per batch
__device__ float g_state[BSZ][4];
__device__ volatile unsigned g_flag[BSZ];   // zero-init; consumer resets -> replay-safe

// ---------------------------------------------------------------------------
// Fully fused, zero-scratch kernel; 512 threads/CTA (float2 per thread) to
// double warps/SM vs the 256-thread variant (grid-limited occupancy fix).
//   CTA (b,h): curr[o][t] for its t-range computed into SMEM (GEMM), then a
//   chunked log-depth scan of
//     syn_t = a*syn_{t-1} + c_t ;  mem_t = m*mem_{t-1} + syn_t
//   Half 1 seeds its warp-composition with half 0's final state (affine scan:
//   seeding the exclusive prefix is exact).
//   Spin safety: producer CTA (2b) is dispatched no later than consumer (2b+1)
//   and is dependency-free, so it always completes; >=2 CTAs/SM co-resident.
// ---------------------------------------------------------------------------
__global__ __launch_bounds__(NTHR, 3)
void snn_fused_kernel(const float* __restrict__ inp,   // [B, I, T]
                      const float* __restrict__ W,     // [O, I]
                      const float* __restrict__ bias,  // [O]
                      const float* __restrict__ alpha,
                      const float* __restrict__ beta,
                      float* __restrict__ out)         // [B, T, O]
{
    __shared__ float  Wsh[OCH][IDIM];
    __shared__ float2 csh[OCH][NTHR];   // slot j = currents for local t [2j,2j+2)
    __shared__ float  Ts[OCH][NW][2];   // warp totals (syn, mem)
    __shared__ float  Es[OCH][NW][2];   // warp exclusive prefixes
    __shared__ float  Bnd[4];           // boundary seed

    const int tid = threadIdx.x;
    const int b   = blockIdx.x >> 1;
    const int h   = blockIdx.x & 1;

    const int tbase = h ? H0LEN : 0;                   // this half's first t
    const int nch   = h ? (H1LEN / 2) : (H0LEN / 2);   // 488 or 512 live chunks
    const int lastj = (H0LEN / 2) - 1;                 // half-0 chunk holding t=1023

    for (int k = tid; k < OCH * IDIM; k += NTHR)
        Wsh[k / IDIM][k % IDIM] = W[k];
    __syncthreads();

    // ======================= phase 1: GEMM into SMEM ==========================
    if (tid < nch) {
        const int t0 = tbase + tid * 2;
        const float* ib = inp + (size_t)b * IDIM * TSTEPS + t0;

        float2 acc0 = make_float2(0.f, 0.f);
        float2 acc1 = make_float2(0.f, 0.f);

        #pragma unroll 7
        for (int i = 0; i < IDIM; i++) {
            const float2 x = __ldcs(reinterpret_cast<const float2*>(ib + (size_t)i * TSTEPS));
            const float w0 = Wsh[0][i];
            const float w1 = Wsh[1][i];
            acc0.x = fmaf(w0, x.x, acc0.x); acc0.y = fmaf(w0, x.y, acc0.y);
            acc1.x = fmaf(w1, x.x, acc1.x); acc1.y = fmaf(w1, x.y, acc1.y);
        }

        const float b0 = bias[0];
        const float b1 = bias[1];
        acc0.x += b0; acc0.y += b0;
        acc1.x += b1; acc1.y += b1;

        csh[0][tid] = acc0;
        csh[1][tid] = acc1;
    } else {
        const float2 z = make_float2(0.f, 0.f);
        csh[0][tid] = z;
        csh[1][tid] = z;
    }
    __syncthreads();

    // ======================= phase 2: scan of this half ======================
    const int j    = tid;               // chunk index 0..511
    const int lane = j & 31;
    const int w    = j >> 5;            // warp 0..15
    const bool live = (j < nch);

    float a[OCH], m[OCH];
    a[0] = __saturatef(alpha[0]); a[1] = __saturatef(alpha[1]);
    m[0] = __saturatef(beta[0]);  m[1] = __saturatef(beta[1]);

    // phase A: chunk currents from SMEM, local scan from zero state
    float c[OCH][CHUNK];
    float vs[OCH], vm[OCH];
    #pragma unroll
    for (int o = 0; o < OCH; o++) {
        const float2 x = csh[o][j];
        c[o][0] = x.x; c[o][1] = x.y;
        float s = 0.f, q = 0.f;
        #pragma unroll
        for (int k = 0; k < CHUNK; k++) {
            s = fmaf(a[o], s, c[o][k]);
            q = fmaf(m[o], q, s);
        }
        vs[o] = s; vm[o] = q;
    }

    // P = M^CHUNK per channel:  M = [[a,0],[a,m]], M^k = [[A,0],[C,B]]
    float PA[OCH], PB[OCH], PC[OCH];
    #pragma unroll
    for (int o = 0; o < OCH; o++) {
        float A = 1.f, B = 1.f, C = 0.f;
        #pragma unroll
        for (int k = 0; k < CHUNK; k++) {
            A = a[o] * A;
            C = fmaf(m[o], C, A);
            B = m[o] * B;
        }
        PA[o] = A; PB[o] = B; PC[o] = C;
    }

    // phase B: Kogge-Stone intra-warp scan; build L = P^lane on the fly
    float LA[OCH] = {1.f, 1.f}, LB[OCH] = {1.f, 1.f}, LC[OCH] = {0.f, 0.f};

    #pragma unroll
    for (int d = 1; d <= 16; d <<= 1) {
        #pragma unroll
        for (int o = 0; o < OCH; o++) {
            if (lane & d) {
                const float nA = LA[o] * PA[o];
                const float nB = LB[o] * PB[o];
                const float nC = fmaf(LC[o], PA[o], LB[o] * PC[o]);
                LA[o] = nA; LB[o] = nB; LC[o] = nC;
            }
        }
        #pragma unroll
        for (int o = 0; o < OCH; o++) {
            const float ws = __shfl_up_sync(0xffffffffu, vs[o], d);
            const float wq = __shfl_up_sync(0xffffffffu, vm[o], d);
            if (lane >= d) {
                vm[o] = fmaf(PC[o], ws, fmaf(PB[o], wq, vm[o]));
                vs[o] = fmaf(PA[o], ws, vs[o]);
            }
        }
        #pragma unroll
        for (int o = 0; o < OCH; o++) {
            PC[o] = PC[o] * (PA[o] + PB[o]);
            PA[o] = PA[o] * PA[o];
            PB[o] = PB[o] * PB[o];
        }
    }
    // P now holds P^(32*CHUNK) = warp-span matrix

    if (lane == 31) {
        #pragma unroll
        for (int o = 0; o < OCH; o++) {
            Ts[o][w][0] = vs[o];
            Ts[o][w][1] = vm[o];
        }
    }

    // boundary seed: half 0 -> zeros; half 1 -> wait for half 0's final state
    if (tid == 0) {
        if (h == 1) {
            while (g_flag[b] == 0u) { /* brief spin; producer dispatched earlier */ }
            __threadfence();            // acquire: order state reads after flag
            Bnd[0] = g_state[b][0];
            Bnd[1] = g_state[b][1];
            Bnd[2] = g_state[b][2];
            Bnd[3] = g_state[b][3];
            g_flag[b] = 0u;             // consume: reset for next graph replay
        } else {
            Bnd[0] = 0.f; Bnd[1] = 0.f; Bnd[2] = 0.f; Bnd[3] = 0.f;
        }
    }
    __syncthreads();

    // serial composition over NW warp totals, seeded with boundary state
    if (j < OCH) {
        const int o = j;
        float Ss = Bnd[2 * o + 0];
        float Sm = Bnd[2 * o + 1];
        #pragma unroll
        for (int k = 0; k < NW; k++) {
            Es[o][k][0] = Ss;
            Es[o][k][1] = Sm;
            const float ts = Ts[o][k][0];
            const float tm = Ts[o][k][1];
            const float ns = fmaf(PA[o], Ss, ts);
            const float nm = fmaf(PC[o], Ss, fmaf(PB[o], Sm, tm));
            Ss = ns; Sm = nm;
        }
    }
    __syncthreads();

    // phase C: chunk prefix = P^lane * E_w + intra-warp exclusive; replay & store
    if (live) {
        float pre_s[OCH], pre_m[OCH];
        #pragma unroll
        for (int o = 0; o < OCH; o++) {
            float Xs = __shfl_up_sync(0xffffffffu, vs[o], 1);
            float Xm = __shfl_up_sync(0xffffffffu, vm[o], 1);
            if (lane == 0) { Xs = 0.f; Xm = 0.f; }
            const float es = Es[o][w][0];
            const float em = Es[o][w][1];
            pre_s[o] = fmaf(LA[o], es, Xs);
            pre_m[o] = fmaf(LC[o], es, fmaf(LB[o], em, Xm));
        }
        float s0 = pre_s[0], q0 = pre_m[0];
        float s1 = pre_s[1], q1 = pre_m[1];

        float r[2 * CHUNK];
        #pragma unroll
        for (int k = 0; k < CHUNK; k++) {
            s0 = fmaf(a[0], s0, c[0][k]); q0 = fmaf(m[0], q0, s0);
            s1 = fmaf(a[1], s1, c[1][k]); q1 = fmaf(m[1], q1, s1);
            r[2 * k + 0] = q0;
            r[2 * k + 1] = q1;
        }

        // out[b][t][o], t = tbase + j*2 : 4 floats = one float4 streaming store
        float4* ob = reinterpret_cast<float4*>(out + ((size_t)b * TSTEPS + tbase + j * 2) * OCH);
        __stcs(ob, make_float4(r[0], r[1], r[2], r[3]));

        // half 0's last chunk publishes the boundary state (after t=1023) for half 1
        if (h == 0 && j == lastj) {
            g_state[b][0] = s0;
            g_state[b][1] = q0;
            g_state[b][2] = s1;
            g_state[b][3] = q1;
            __threadfence();            // release: state before flag
            g_flag[b] = 1u;
        }
    }
}

extern "C" void kernel_launch(void* const* d_in, const int* in_sizes, int n_in,
                              void* d_out, int out_size)
{
    const float* inp   = (const float*)d_in[0]; // [256,182,2000]
    const float* W     = (const float*)d_in[1]; // [2,182]
    const float* bias  = (const float*)d_in[2]; // [2]
    const float* alpha = (const float*)d_in[3]; // [2]
    const float* beta  = (const float*)d_in[4]; // [2]
    float* out = (float*)d_out;                 // [256,2000,2]

    snn_fused_kernel<<<GRID, NTHR>>>(inp, W, bias, alpha, beta, out);
}

// round 11
// speedup vs baseline: 1.2804x; 1.2804x over previous
#include <cuda_runtime.h>

// Problem constants
#define BSZ     256
#define IDIM    182
#define IHALF   91           // dual-stream reduction: i and i+91; 91 = 7*13
#define TSTEPS  2000
#define H0LEN   1024         // half 0: t in [0,1024)    -- 128B-aligned rows
#define H1LEN   976          // half 1: t in [1024,2000) -- base offset 4096B, aligned
#define OCH     2
#define CHUNK   4            // steps per thread in scan phase
#define GRID    (BSZ * 2)    // CTA 2b+h: batch b, t-half h

// boundary handoff: half-0 final state (syn0,mem0,syn1,mem1) + flag per batch
__device__ float g_state[BSZ][4];
__device__ volatile unsigned g_flag[BSZ];   // zero-init; consumer resets -> replay-safe

// ---------------------------------------------------------------------------
// Fully fused, zero-scratch kernel with line-aligned halves and a dual-stream
// i-reduction (two independent LDG.128 streams per thread -> ~2x front-batched
// loads in flight within the 64-reg / 4-CTA-per-SM envelope).
//   CTA (b,h): curr[o][t] for its t-range computed into SMEM (GEMM), then a
//   chunked log-depth scan of
//     syn_t = a*syn_{t-1} + c_t ;  mem_t = m*mem_{t-1} + syn_t
//   Half 1 seeds its warp-composition with half 0's final state (affine scan:
//   seeding the exclusive prefix is exact). Half 0 publishes that state via a
//   per-batch flag; the brief consumer spin is safe because
//   __launch_bounds__(256,4) guarantees all 512 CTAs co-resident (148*4=592).
// ---------------------------------------------------------------------------
__global__ __launch_bounds__(256, 4)
void snn_fused_kernel(const float* __restrict__ inp,   // [B, I, T]
                      const float* __restrict__ W,     // [O, I]
                      const float* __restrict__ bias,  // [O]
                      const float* __restrict__ alpha,
                      const float* __restrict__ beta,
                      float* __restrict__ out)         // [B, T, O]
{
    __shared__ float  Wsh[OCH][IDIM];
    __shared__ float4 csh[OCH][256];    // slot j = currents for local t [4j,4j+4)
    __shared__ float  Ts[OCH][8][2];    // warp totals (syn, mem)
    __shared__ float  Es[OCH][8][2];    // warp exclusive prefixes
    __shared__ float  Bnd[4];           // boundary seed

    const int tid = threadIdx.x;
    const int b   = blockIdx.x >> 1;
    const int h   = blockIdx.x & 1;

    const int tbase = h ? H0LEN : 0;                   // this half's first t
    const int nch   = h ? (H1LEN / 4) : (H0LEN / 4);   // 244 or 256 live chunks
    const int lastj = (H0LEN / 4) - 1;                 // half-0 chunk holding t=1023

    for (int k = tid; k < OCH * IDIM; k += 256)
        Wsh[k / IDIM][k % IDIM] = W[k];
    __syncthreads();

    // ======================= phase 1: GEMM into SMEM ==========================
    if (tid < nch) {
        const int t0 = tbase + tid * 4;
        const float* ib_lo = inp + (size_t)b * IDIM * TSTEPS + t0;
        const float* ib_hi = ib_lo + (size_t)IHALF * TSTEPS;

        float4 acc0 = make_float4(0.f, 0.f, 0.f, 0.f);
        float4 acc1 = make_float4(0.f, 0.f, 0.f, 0.f);

        #pragma unroll 7
        for (int i = 0; i < IHALF; i++) {
            const float4 xl = __ldcs(reinterpret_cast<const float4*>(ib_lo + (size_t)i * TSTEPS));
            const float4 xh = __ldcs(reinterpret_cast<const float4*>(ib_hi + (size_t)i * TSTEPS));
            const float wl0 = Wsh[0][i];
            const float wl1 = Wsh[1][i];
            const float wh0 = Wsh[0][i + IHALF];
            const float wh1 = Wsh[1][i + IHALF];
            acc0.x = fmaf(wl0, xl.x, acc0.x); acc0.y = fmaf(wl0, xl.y, acc0.y);
            acc0.z = fmaf(wl0, xl.z, acc0.z); acc0.w = fmaf(wl0, xl.w, acc0.w);
            acc1.x = fmaf(wl1, xl.x, acc1.x); acc1.y = fmaf(wl1, xl.y, acc1.y);
            acc1.z = fmaf(wl1, xl.z, acc1.z); acc1.w = fmaf(wl1, xl.w, acc1.w);
            acc0.x = fmaf(wh0, xh.x, acc0.x); acc0.y = fmaf(wh0, xh.y, acc0.y);
            acc0.z = fmaf(wh0, xh.z, acc0.z); acc0.w = fmaf(wh0, xh.w, acc0.w);
            acc1.x = fmaf(wh1, xh.x, acc1.x); acc1.y = fmaf(wh1, xh.y, acc1.y);
            acc1.z = fmaf(wh1, xh.z, acc1.z); acc1.w = fmaf(wh1, xh.w, acc1.w);
        }

        const float b0 = bias[0];
        const float b1 = bias[1];
        acc0.x += b0; acc0.y += b0; acc0.z += b0; acc0.w += b0;
        acc1.x += b1; acc1.y += b1; acc1.z += b1; acc1.w += b1;

        csh[0][tid] = acc0;
        csh[1][tid] = acc1;
    } else {
        const float4 z = make_float4(0.f, 0.f, 0.f, 0.f);
        csh[0][tid] = z;
        csh[1][tid] = z;
    }
    __syncthreads();

    // ======================= phase 2: scan of this half ======================
    const int j    = tid;               // chunk index 0..255
    const int lane = j & 31;
    const int w    = j >> 5;
    const bool live = (j < nch);

    float a[OCH], m[OCH];
    a[0] = __saturatef(alpha[0]); a[1] = __saturatef(alpha[1]);
    m[0] = __saturatef(beta[0]);  m[1] = __saturatef(beta[1]);

    // phase A: chunk currents from SMEM, local scan from zero state
    float c[OCH][CHUNK];
    float vs[OCH], vm[OCH];
    #pragma unroll
    for (int o = 0; o < OCH; o++) {
        const float4 x = csh[o][j];
        c[o][0] = x.x; c[o][1] = x.y; c[o][2] = x.z; c[o][3] = x.w;
        float s = 0.f, q = 0.f;
        #pragma unroll
        for (int k = 0; k < CHUNK; k++) {
            s = fmaf(a[o], s, c[o][k]);
            q = fmaf(m[o], q, s);
        }
        vs[o] = s; vm[o] = q;
    }

    // P = M^CHUNK per channel:  M = [[a,0],[a,m]], M^k = [[A,0],[C,B]]
    float PA[OCH], PB[OCH], PC[OCH];
    #pragma unroll
    for (int o = 0; o < OCH; o++) {
        float A = 1.f, B = 1.f, C = 0.f;
        #pragma unroll
        for (int k = 0; k < CHUNK; k++) {
            A = a[o] * A;
            C = fmaf(m[o], C, A);
            B = m[o] * B;
        }
        PA[o] = A; PB[o] = B; PC[o] = C;
    }

    // phase B: Kogge-Stone intra-warp scan; build L = P^lane on the fly
    float LA[OCH] = {1.f, 1.f}, LB[OCH] = {1.f, 1.f}, LC[OCH] = {0.f, 0.f};

    #pragma unroll
    for (int d = 1; d <= 16; d <<= 1) {
        #pragma unroll
        for (int o = 0; o < OCH; o++) {
            if (lane & d) {
                const float nA = LA[o] * PA[o];
                const float nB = LB[o] * PB[o];
                const float nC = fmaf(LC[o], PA[o], LB[o] * PC[o]);
                LA[o] = nA; LB[o] = nB; LC[o] = nC;
            }
        }
        #pragma unroll
        for (int o = 0; o < OCH; o++) {
            const float ws = __shfl_up_sync(0xffffffffu, vs[o], d);
            const float wq = __shfl_up_sync(0xffffffffu, vm[o], d);
            if (lane >= d) {
                vm[o] = fmaf(PC[o], ws, fmaf(PB[o], wq, vm[o]));
                vs[o] = fmaf(PA[o], ws, vs[o]);
            }
        }
        #pragma unroll
        for (int o = 0; o < OCH; o++) {
            PC[o] = PC[o] * (PA[o] + PB[o]);
            PA[o] = PA[o] * PA[o];
            PB[o] = PB[o] * PB[o];
        }
    }
    // P now holds P^32 (warp-span matrix)

    if (lane == 31) {
        #pragma unroll
        for (int o = 0; o < OCH; o++) {
            Ts[o][w][0] = vs[o];
            Ts[o][w][1] = vm[o];
        }
    }

    // boundary seed: half 0 -> zeros; half 1 -> wait for half 0's final state
    if (tid == 0) {
        if (h == 1) {
            while (g_flag[b] == 0u) { /* brief spin; producer co-resident */ }
            __threadfence();            // acquire: order state reads after flag
            Bnd[0] = g_state[b][0];
            Bnd[1] = g_state[b][1];
            Bnd[2] = g_state[b][2];
            Bnd[3] = g_state[b][3];
            g_flag[b] = 0u;             // consume: reset for next graph replay
        } else {
            Bnd[0] = 0.f; Bnd[1] = 0.f; Bnd[2] = 0.f; Bnd[3] = 0.f;
        }
    }
    __syncthreads();

    // serial composition over 8 warp totals, seeded with boundary state
    if (j < OCH) {
        const int o = j;
        float Ss = Bnd[2 * o + 0];
        float Sm = Bnd[2 * o + 1];
        #pragma unroll
        for (int k = 0; k < 8; k++) {
            Es[o][k][0] = Ss;
            Es[o][k][1] = Sm;
            const float ts = Ts[o][k][0];
            const float tm = Ts[o][k][1];
            const float ns = fmaf(PA[o], Ss, ts);
            const float nm = fmaf(PC[o], Ss, fmaf(PB[o], Sm, tm));
            Ss = ns; Sm = nm;
        }
    }
    __syncthreads();

    // phase C: chunk prefix = P^lane * E_w + intra-warp exclusive; replay & store
    if (live) {
        float pre_s[OCH], pre_m[OCH];
        #pragma unroll
        for (int o = 0; o < OCH; o++) {
            float Xs = __shfl_up_sync(0xffffffffu, vs[o], 1);
            float Xm = __shfl_up_sync(0xffffffffu, vm[o], 1);
            if (lane == 0) { Xs = 0.f; Xm = 0.f; }
            const float es = Es[o][w][0];
            const float em = Es[o][w][1];
            pre_s[o] = fmaf(LA[o], es, Xs);
            pre_m[o] = fmaf(LC[o], es, fmaf(LB[o], em, Xm));
        }
        float s0 = pre_s[0], q0 = pre_m[0];
        float s1 = pre_s[1], q1 = pre_m[1];

        float r[2 * CHUNK];
        #pragma unroll
        for (int k = 0; k < CHUNK; k++) {
            s0 = fmaf(a[0], s0, c[0][k]); q0 = fmaf(m[0], q0, s0);
            s1 = fmaf(a[1], s1, c[1][k]); q1 = fmaf(m[1], q1, s1);
            r[2 * k + 0] = q0;
            r[2 * k + 1] = q1;
        }

        // out[b][t][o], t = tbase + j*4 : 8 floats = two float4 streaming stores
        float4* ob = reinterpret_cast<float4*>(out + ((size_t)b * TSTEPS + tbase + j * 4) * OCH);
        __stcs(ob + 0, make_float4(r[0], r[1], r[2], r[3]));
        __stcs(ob + 1, make_float4(r[4], r[5], r[6], r[7]));

        // half 0's last chunk publishes the boundary state (after t=1023) for half 1
        if (h == 0 && j == lastj) {
            g_state[b][0] = s0;
            g_state[b][1] = q0;
            g_state[b][2] = s1;
            g_state[b][3] = q1;
            __threadfence();            // release: state before flag
            g_flag[b] = 1u;
        }
    }
}

extern "C" void kernel_launch(void* const* d_in, const int* in_sizes, int n_in,
                              void* d_out, int out_size)
{
    const float* inp   = (const float*)d_in[0]; // [256,182,2000]
    const float* W     = (const float*)d_in[1]; // [2,182]
    const float* bias  = (const float*)d_in[2]; // [2]
    const float* alpha = (const float*)d_in[3]; // [2]
    const float* beta  = (const float*)d_in[4]; // [2]
    float* out = (float*)d_out;                 // [256,2000,2]

    snn_fused_kernel<<<GRID, 256>>>(inp, W, bias, alpha, beta, out);
}